// round 2
// baseline (speedup 1.0000x reference)
#include <cuda_runtime.h>
#include <math.h>

#define NB 8
#define NS 1024
#define NE 1024
#define NH 16
#define ND 64
#define NM (NB*NS)   // 8192 rows

// Scratch (device globals: allocation-free per harness rules)
__device__ float g_qh[NB*NH*NS*ND];   // [B,H,S,D]
__device__ float g_kh[NB*NH*NS*ND];
__device__ float g_vh[NB*NH*NS*ND];
__device__ float g_ctx[NB*NS*NE];     // [B,S,E] (heads concatenated)

// ---------------------------------------------------------------------------
// Projection GEMM: out[b,h,s,e] = sum_d X[b,s,d] * W[h,d,e] + bias[h,e]
// Tile: 64 (M) x 64 (N=full head) x 32 (K). 256 threads, 4x4 micro-tile.
// which: 0->g_qh, 1->g_kh, 2->g_vh
// ---------------------------------------------------------------------------
__global__ __launch_bounds__(256) void proj_kernel(
    const float* __restrict__ X, const float* __restrict__ W,
    const float* __restrict__ bias, int which)
{
    __shared__ __align__(16) float As[64][33];   // pad -> conflict-free column reads
    __shared__ __align__(16) float Bs[32][64];

    float* out = (which == 0) ? g_qh : (which == 1) ? g_kh : g_vh;

    const int h  = blockIdx.y;
    const int m0 = blockIdx.x * 64;
    const int tid = threadIdx.x;
    const int ty = tid >> 4, tx = tid & 15;
    const int r = ty * 4, c = tx * 4;
    const float* Wh = W + (size_t)h * (NE * ND);

    float acc[4][4];
#pragma unroll
    for (int i = 0; i < 4; i++)
#pragma unroll
        for (int j = 0; j < 4; j++) acc[i][j] = 0.f;

    const int arow = tid >> 3;            // 0..31
    const int acol = (tid & 7) * 4;       // 0..28
    const int brow = tid >> 4;            // 0..15
    const int bcol = (tid & 15) * 4;      // 0..60

    for (int k0 = 0; k0 < NE; k0 += 32) {
        float4 a0 = *(const float4*)(X + (size_t)(m0 + arow) * NE + k0 + acol);
        float4 a1 = *(const float4*)(X + (size_t)(m0 + arow + 32) * NE + k0 + acol);
        float4 b0 = *(const float4*)(Wh + (size_t)(k0 + brow) * ND + bcol);
        float4 b1 = *(const float4*)(Wh + (size_t)(k0 + brow + 16) * ND + bcol);

        As[arow][acol+0] = a0.x; As[arow][acol+1] = a0.y;
        As[arow][acol+2] = a0.z; As[arow][acol+3] = a0.w;
        As[arow+32][acol+0] = a1.x; As[arow+32][acol+1] = a1.y;
        As[arow+32][acol+2] = a1.z; As[arow+32][acol+3] = a1.w;
        *(float4*)&Bs[brow][bcol]      = b0;
        *(float4*)&Bs[brow + 16][bcol] = b1;
        __syncthreads();

#pragma unroll
        for (int kk = 0; kk < 32; kk++) {
            float av[4];
#pragma unroll
            for (int i = 0; i < 4; i++) av[i] = As[r + i][kk];
            float4 bv = *(const float4*)&Bs[kk][c];
#pragma unroll
            for (int i = 0; i < 4; i++) {
                acc[i][0] += av[i] * bv.x;
                acc[i][1] += av[i] * bv.y;
                acc[i][2] += av[i] * bv.z;
                acc[i][3] += av[i] * bv.w;
            }
        }
        __syncthreads();
    }

    float4 bb = *(const float4*)(bias + h * ND + c);
#pragma unroll
    for (int i = 0; i < 4; i++) {
        int m = m0 + r + i;
        int b = m >> 10, s = m & 1023;
        float4 v;
        v.x = acc[i][0] + bb.x; v.y = acc[i][1] + bb.y;
        v.z = acc[i][2] + bb.z; v.w = acc[i][3] + bb.w;
        *(float4*)(out + (size_t)(b * NH + h) * (NS * ND) + (size_t)s * ND + c) = v;
    }
}

// ---------------------------------------------------------------------------
// Flash attention per (b,h): 64-row Q tile per block, loop over 16 K/V tiles.
// 256 threads: thread = (row = tid>>2, q4 = tid&3).
//   scores: thread owns k-cols [q4*16, q4*16+16)   (K smem XOR-swizzled by k>>4)
//   output: thread owns e-cols { t*16 + q4*4 .. +3 : t=0..3 } (conflict-free V reads)
// ---------------------------------------------------------------------------
__global__ __launch_bounds__(256) void attn_kernel()
{
    __shared__ __align__(16) float Ks[64][64];   // xor-swizzled columns
    __shared__ __align__(16) float Vs[64][64];
    __shared__ __align__(16) float Ps[64][65];   // pad 65 -> conflict-free col reads

    const int bh = blockIdx.y;
    const int s0 = blockIdx.x * 64;
    const float* Qp = g_qh + (size_t)bh * (NS * ND);
    const float* Kp = g_kh + (size_t)bh * (NS * ND);
    const float* Vp = g_vh + (size_t)bh * (NS * ND);

    const int tid = threadIdx.x;
    const int row = tid >> 2;   // 0..63 (q row in tile)
    const int q4  = tid & 3;

    // Q row into registers (64 floats)
    float qreg[64];
    {
        const float* qs = Qp + (size_t)(s0 + row) * ND;
#pragma unroll
        for (int d4 = 0; d4 < 16; d4++) {
            float4 t = *(const float4*)(qs + d4 * 4);
            qreg[d4*4+0] = t.x; qreg[d4*4+1] = t.y;
            qreg[d4*4+2] = t.z; qreg[d4*4+3] = t.w;
        }
    }

    float m_i = -1e30f, l_i = 0.f;
    float o[16];
#pragma unroll
    for (int i = 0; i < 16; i++) o[i] = 0.f;
    const float scale = 0.125f;  // 1/sqrt(64)

    for (int kt = 0; kt < 16; kt++) {
        // load K (swizzled) and V tiles
#pragma unroll
        for (int i = 0; i < 4; i++) {
            int fi = tid + i * 256;
            int rr = fi >> 4;
            int c4 = fi & 15;
            float4 kv = *(const float4*)(Kp + (size_t)(kt * 64 + rr) * ND + c4 * 4);
            float4 vv = *(const float4*)(Vp + (size_t)(kt * 64 + rr) * ND + c4 * 4);
            *(float4*)&Ks[rr][(c4 ^ (rr >> 4)) * 4] = kv;
            *(float4*)&Vs[rr][c4 * 4] = vv;
        }
        __syncthreads();

        // scores for kl = q4*16 + j, j in [0,16)
        float p[16];
#pragma unroll
        for (int jc = 0; jc < 4; jc++) {
            float a0 = 0.f, a1 = 0.f, a2 = 0.f, a3 = 0.f;
            const int kl0 = q4 * 16 + jc * 4;
#pragma unroll
            for (int d4 = 0; d4 < 16; d4++) {
                const int pc = (d4 ^ q4) * 4;   // matches store swizzle (kl>>4 == q4)
                float4 k0v = *(const float4*)&Ks[kl0 + 0][pc];
                float4 k1v = *(const float4*)&Ks[kl0 + 1][pc];
                float4 k2v = *(const float4*)&Ks[kl0 + 2][pc];
                float4 k3v = *(const float4*)&Ks[kl0 + 3][pc];
                float q0 = qreg[d4*4+0], q1 = qreg[d4*4+1];
                float q2 = qreg[d4*4+2], q3 = qreg[d4*4+3];
                a0 += q0*k0v.x + q1*k0v.y + q2*k0v.z + q3*k0v.w;
                a1 += q0*k1v.x + q1*k1v.y + q2*k1v.z + q3*k1v.w;
                a2 += q0*k2v.x + q1*k2v.y + q2*k2v.z + q3*k2v.w;
                a3 += q0*k3v.x + q1*k3v.y + q2*k3v.z + q3*k3v.w;
            }
            p[jc*4+0] = a0 * scale; p[jc*4+1] = a1 * scale;
            p[jc*4+2] = a2 * scale; p[jc*4+3] = a3 * scale;
        }

        // online softmax (row state replicated across the 4-thread quad)
        float tmax = p[0];
#pragma unroll
        for (int j = 1; j < 16; j++) tmax = fmaxf(tmax, p[j]);
        tmax = fmaxf(tmax, __shfl_xor_sync(0xffffffffu, tmax, 1));
        tmax = fmaxf(tmax, __shfl_xor_sync(0xffffffffu, tmax, 2));
        float m_new = fmaxf(m_i, tmax);
        float alpha = __expf(m_i - m_new);
        float lsum = 0.f;
#pragma unroll
        for (int j = 0; j < 16; j++) { p[j] = __expf(p[j] - m_new); lsum += p[j]; }
        lsum += __shfl_xor_sync(0xffffffffu, lsum, 1);
        lsum += __shfl_xor_sync(0xffffffffu, lsum, 2);
        l_i = l_i * alpha + lsum;
        m_i = m_new;
#pragma unroll
        for (int i = 0; i < 16; i++) o[i] *= alpha;

        // publish P tile
#pragma unroll
        for (int j = 0; j < 16; j++) Ps[row][q4 * 16 + j] = p[j];
        __syncthreads();

        // O += P @ V  (thread e-cols: t*16 + q4*4 .. +3)
#pragma unroll
        for (int k = 0; k < 64; k++) {
            float pk = Ps[row][k];
#pragma unroll
            for (int t = 0; t < 4; t++) {
                float4 vv = *(const float4*)&Vs[k][t * 16 + q4 * 4];
                o[t*4+0] += pk * vv.x; o[t*4+1] += pk * vv.y;
                o[t*4+2] += pk * vv.z; o[t*4+3] += pk * vv.w;
            }
        }
        __syncthreads();
    }

    // normalize + write ctx[b, s, h*64 + e]
    float inv = 1.f / l_i;
    int b = bh >> 4, h = bh & 15;
    float* dst = g_ctx + (size_t)(b * NS + s0 + row) * NE + h * ND;
#pragma unroll
    for (int t = 0; t < 4; t++) {
        float4 v;
        v.x = o[t*4+0] * inv; v.y = o[t*4+1] * inv;
        v.z = o[t*4+2] * inv; v.w = o[t*4+3] * inv;
        *(float4*)(dst + t * 16 + q4 * 4) = v;
    }
}

// ---------------------------------------------------------------------------
// Output GEMM: out[m,n] = sum_k ctx[m,k] * Wo[k,n] + bo[n]
// ---------------------------------------------------------------------------
__global__ __launch_bounds__(256) void out_kernel(
    const float* __restrict__ Wo, const float* __restrict__ bo,
    float* __restrict__ out)
{
    __shared__ __align__(16) float As[64][33];
    __shared__ __align__(16) float Bs[32][64];

    const int n0 = blockIdx.y * 64;
    const int m0 = blockIdx.x * 64;
    const int tid = threadIdx.x;
    const int ty = tid >> 4, tx = tid & 15;
    const int r = ty * 4, c = tx * 4;

    float acc[4][4];
#pragma unroll
    for (int i = 0; i < 4; i++)
#pragma unroll
        for (int j = 0; j < 4; j++) acc[i][j] = 0.f;

    const int arow = tid >> 3;
    const int acol = (tid & 7) * 4;
    const int brow = tid >> 4;
    const int bcol = (tid & 15) * 4;

    for (int k0 = 0; k0 < NE; k0 += 32) {
        float4 a0 = *(const float4*)(g_ctx + (size_t)(m0 + arow) * NE + k0 + acol);
        float4 a1 = *(const float4*)(g_ctx + (size_t)(m0 + arow + 32) * NE + k0 + acol);
        float4 b0 = *(const float4*)(Wo + (size_t)(k0 + brow) * NE + n0 + bcol);
        float4 b1 = *(const float4*)(Wo + (size_t)(k0 + brow + 16) * NE + n0 + bcol);

        As[arow][acol+0] = a0.x; As[arow][acol+1] = a0.y;
        As[arow][acol+2] = a0.z; As[arow][acol+3] = a0.w;
        As[arow+32][acol+0] = a1.x; As[arow+32][acol+1] = a1.y;
        As[arow+32][acol+2] = a1.z; As[arow+32][acol+3] = a1.w;
        *(float4*)&Bs[brow][bcol]      = b0;
        *(float4*)&Bs[brow + 16][bcol] = b1;
        __syncthreads();

#pragma unroll
        for (int kk = 0; kk < 32; kk++) {
            float av[4];
#pragma unroll
            for (int i = 0; i < 4; i++) av[i] = As[r + i][kk];
            float4 bv = *(const float4*)&Bs[kk][c];
#pragma unroll
            for (int i = 0; i < 4; i++) {
                acc[i][0] += av[i] * bv.x;
                acc[i][1] += av[i] * bv.y;
                acc[i][2] += av[i] * bv.z;
                acc[i][3] += av[i] * bv.w;
            }
        }
        __syncthreads();
    }

    float4 bb = *(const float4*)(bo + n0 + c);
#pragma unroll
    for (int i = 0; i < 4; i++) {
        float4 v;
        v.x = acc[i][0] + bb.x; v.y = acc[i][1] + bb.y;
        v.z = acc[i][2] + bb.z; v.w = acc[i][3] + bb.w;
        *(float4*)(out + (size_t)(m0 + r + i) * NE + n0 + c) = v;
    }
}

// ---------------------------------------------------------------------------
extern "C" void kernel_launch(void* const* d_in, const int* in_sizes, int n_in,
                              void* d_out, int out_size)
{
    const float* q  = (const float*)d_in[0];
    const float* k  = (const float*)d_in[1];
    const float* v  = (const float*)d_in[2];
    const float* Wq = (const float*)d_in[3];
    const float* bq = (const float*)d_in[4];
    const float* Wk = (const float*)d_in[5];
    const float* bk = (const float*)d_in[6];
    const float* Wv = (const float*)d_in[7];
    const float* bv = (const float*)d_in[8];
    const float* Wo = (const float*)d_in[9];
    const float* bo = (const float*)d_in[10];
    float* out = (float*)d_out;

    dim3 pgrid(NM / 64, NH);
    proj_kernel<<<pgrid, 256>>>(q, Wq, bq, 0);
    proj_kernel<<<pgrid, 256>>>(k, Wk, bk, 1);
    proj_kernel<<<pgrid, 256>>>(v, Wv, bv, 2);

    attn_kernel<<<dim3(NS / 64, NB * NH), 256>>>();

    out_kernel<<<dim3(NM / 64, NE / 64), 256>>>(Wo, bo, out);
}

// round 4
// speedup vs baseline: 1.3685x; 1.3685x over previous
#include <cuda_runtime.h>
#include <math.h>
#include <stdint.h>

#define NB 8
#define NS 1024
#define NE 1024
#define NH 16
#define ND 64
#define NM (NB*NS)

// ---------------- device-global scratch (allocation-free) ------------------
__device__ float g_qh[NB*NH*NS*ND];
__device__ float g_kh[NB*NH*NS*ND];
__device__ float g_vh[NB*NH*NS*ND];
__device__ float g_ctx[NB*NS*NE];
__device__ float g_wqT[NH*ND*NE];   // [n=h*64+e][k]
__device__ float g_wkT[NH*ND*NE];
__device__ float g_wvT[NH*ND*NE];
__device__ float g_woT[NE*NE];      // [n][k]

__device__ __forceinline__ float tf32rna(float x) {
    uint32_t u;
    asm("cvt.rna.tf32.f32 %0, %1;" : "=r"(u) : "f"(x));
    return __uint_as_float(u);
}

// ---------------- GEMM geometry --------------------------------------------
// CTA tile 128x128, K-chunk 32, smem stride 36 floats (bank-conflict-free frags)
#define TSTRIDE 36
#define TILEF  (128*TSTRIDE)          // floats per matrix tile
#define STAGEF (2*TILEF)              // A + B per stage
#define GSMEM_BYTES (2*STAGEF*4)      // 73728 bytes

// ---------------------------------------------------------------------------
// C[m0:+128, n0:+128] = A[8192,1024] @ BT[1024,1024]^T + bias  (tf32 mma.sync)
// bsel: 0..2 -> g_w{q,k,v}T, 3 -> g_woT
// osel: 0..2 -> scatter to g_{q,k,v}h [B,H,S,D], 3 -> Odirect [8192,1024]
// ---------------------------------------------------------------------------
__global__ __launch_bounds__(256, 2) void gemm_mma(
    const float* __restrict__ Ain, const float* __restrict__ bias,
    float* __restrict__ Odirect, int bsel, int osel)
{
    extern __shared__ float sm[];
    const int tid  = threadIdx.x;
    const int wid  = tid >> 5;
    const int lane = tid & 31;
    const int g    = lane >> 2;     // groupID (0..7)
    const int t    = lane & 3;      // threadID in group (0..3)
    const int m0 = blockIdx.x * 128;
    const int n0 = blockIdx.y * 128;
    const int warp_m = (wid >> 2) * 64;   // 0 or 64
    const int warp_n = (wid & 3) * 32;    // 0,32,64,96

    const float* A  = Ain ? Ain : g_ctx;
    const float* BT = (bsel == 0) ? g_wqT : (bsel == 1) ? g_wkT :
                      (bsel == 2) ? g_wvT : g_woT;

    float d[4][4][4];
#pragma unroll
    for (int mi = 0; mi < 4; mi++)
#pragma unroll
        for (int ni = 0; ni < 4; ni++)
#pragma unroll
            for (int j = 0; j < 4; j++) d[mi][ni][j] = 0.f;

    // ---- chunk loader: LDG fp32 -> cvt.rna.tf32 -> STS (stride 36) ----
    auto load_chunk = [&](int c, int s) {
        const int k0 = c * 32;
        float* As = sm + s * STAGEF;
        float* Bs = sm + s * STAGEF + TILEF;
#pragma unroll
        for (int i = 0; i < 4; i++) {
            int idx = tid + i * 256;
            int row = idx >> 3;
            int c4  = idx & 7;
            float4 va = *(const float4*)(A  + (size_t)(m0 + row) * NE + k0 + c4 * 4);
            float4 vb = *(const float4*)(BT + (size_t)(n0 + row) * NE + k0 + c4 * 4);
            float4 ta, tb;
            ta.x = tf32rna(va.x); ta.y = tf32rna(va.y);
            ta.z = tf32rna(va.z); ta.w = tf32rna(va.w);
            tb.x = tf32rna(vb.x); tb.y = tf32rna(vb.y);
            tb.z = tf32rna(vb.z); tb.w = tf32rna(vb.w);
            *(float4*)(As + row * TSTRIDE + c4 * 4) = ta;
            *(float4*)(Bs + row * TSTRIDE + c4 * 4) = tb;
        }
    };

    load_chunk(0, 0);

    for (int c = 0; c < 32; c++) {
        __syncthreads();
        if (c < 31) load_chunk(c + 1, (c + 1) & 1);

        const float* As = sm + (c & 1) * STAGEF + (warp_m + g) * TSTRIDE;
        const float* Bs = sm + (c & 1) * STAGEF + TILEF + (warp_n + g) * TSTRIDE;
#pragma unroll
        for (int ks = 0; ks < 4; ks++) {
            const int k0 = ks * 8 + t;
            uint32_t a[4][4];
#pragma unroll
            for (int mi = 0; mi < 4; mi++) {
                const float* ap = As + mi * 16 * TSTRIDE + k0;
                a[mi][0] = __float_as_uint(ap[0]);
                a[mi][1] = __float_as_uint(ap[8 * TSTRIDE]);
                a[mi][2] = __float_as_uint(ap[4]);
                a[mi][3] = __float_as_uint(ap[8 * TSTRIDE + 4]);
            }
            uint32_t b[4][2];
#pragma unroll
            for (int ni = 0; ni < 4; ni++) {
                const float* bp = Bs + ni * 8 * TSTRIDE + k0;
                b[ni][0] = __float_as_uint(bp[0]);
                b[ni][1] = __float_as_uint(bp[4]);
            }
#pragma unroll
            for (int mi = 0; mi < 4; mi++)
#pragma unroll
                for (int ni = 0; ni < 4; ni++) {
                    asm volatile(
                        "mma.sync.aligned.m16n8k8.row.col.f32.tf32.tf32.f32 "
                        "{%0,%1,%2,%3}, {%4,%5,%6,%7}, {%8,%9}, {%0,%1,%2,%3};"
                        : "+f"(d[mi][ni][0]), "+f"(d[mi][ni][1]),
                          "+f"(d[mi][ni][2]), "+f"(d[mi][ni][3])
                        : "r"(a[mi][0]), "r"(a[mi][1]), "r"(a[mi][2]), "r"(a[mi][3]),
                          "r"(b[ni][0]), "r"(b[ni][1]));
                }
        }
    }

    // ---- epilogue: bias + store ----
    float* ob = (osel == 0) ? g_qh : (osel == 1) ? g_kh :
                (osel == 2) ? g_vh : Odirect;
#pragma unroll
    for (int mi = 0; mi < 4; mi++) {
#pragma unroll
        for (int ni = 0; ni < 4; ni++) {
            const int r0  = m0 + warp_m + mi * 16 + g;
            const int r1  = r0 + 8;
            const int col = n0 + warp_n + ni * 8 + t * 2;
            const float bx = bias[col], by = bias[col + 1];
            float2 v0, v1;
            v0.x = d[mi][ni][0] + bx; v0.y = d[mi][ni][1] + by;
            v1.x = d[mi][ni][2] + bx; v1.y = d[mi][ni][3] + by;
            if (osel < 3) {
                const int h = col >> 6, e = col & 63;
                float* d0 = ob + ((size_t)((r0 >> 10) * NH + h) * NS + (r0 & 1023)) * ND + e;
                float* d1 = ob + ((size_t)((r1 >> 10) * NH + h) * NS + (r1 & 1023)) * ND + e;
                *(float2*)d0 = v0;
                *(float2*)d1 = v1;
            } else {
                *(float2*)(ob + (size_t)r0 * NE + col) = v0;
                *(float2*)(ob + (size_t)r1 * NE + col) = v1;
            }
        }
    }
}

// ---------------------------------------------------------------------------
// Transpose per z-slice: out[z][c][r] = in[z][r][c]
// ---------------------------------------------------------------------------
__global__ void transpose_kernel(const float* __restrict__ in, int sel, int R, int C)
{
    __shared__ float tbuf[32][33];
    float* out = (sel == 0) ? g_wqT : (sel == 1) ? g_wkT : (sel == 2) ? g_wvT : g_woT;
    const float* I = in  + (size_t)blockIdx.z * R * C;
    float*       O = out + (size_t)blockIdx.z * R * C;
    int c0 = blockIdx.x * 32, r0 = blockIdx.y * 32;
#pragma unroll
    for (int j = threadIdx.y; j < 32; j += 8)
        tbuf[j][threadIdx.x] = I[(size_t)(r0 + j) * C + c0 + threadIdx.x];
    __syncthreads();
#pragma unroll
    for (int j = threadIdx.y; j < 32; j += 8)
        O[(size_t)(c0 + j) * R + r0 + threadIdx.x] = tbuf[threadIdx.x][j];
}

// ---------------------------------------------------------------------------
// Flash attention per (b,h) — unchanged from round 1 (fp32, passing).
// ---------------------------------------------------------------------------
__global__ __launch_bounds__(256) void attn_kernel()
{
    __shared__ __align__(16) float Ks[64][64];
    __shared__ __align__(16) float Vs[64][64];
    __shared__ __align__(16) float Ps[64][65];

    const int bh = blockIdx.y;
    const int s0 = blockIdx.x * 64;
    const float* Qp = g_qh + (size_t)bh * (NS * ND);
    const float* Kp = g_kh + (size_t)bh * (NS * ND);
    const float* Vp = g_vh + (size_t)bh * (NS * ND);

    const int tid = threadIdx.x;
    const int row = tid >> 2;
    const int q4  = tid & 3;

    float qreg[64];
    {
        const float* qs = Qp + (size_t)(s0 + row) * ND;
#pragma unroll
        for (int d4 = 0; d4 < 16; d4++) {
            float4 t = *(const float4*)(qs + d4 * 4);
            qreg[d4*4+0] = t.x; qreg[d4*4+1] = t.y;
            qreg[d4*4+2] = t.z; qreg[d4*4+3] = t.w;
        }
    }

    float m_i = -1e30f, l_i = 0.f;
    float o[16];
#pragma unroll
    for (int i = 0; i < 16; i++) o[i] = 0.f;
    const float scale = 0.125f;

    for (int kt = 0; kt < 16; kt++) {
#pragma unroll
        for (int i = 0; i < 4; i++) {
            int fi = tid + i * 256;
            int rr = fi >> 4;
            int c4 = fi & 15;
            float4 kv = *(const float4*)(Kp + (size_t)(kt * 64 + rr) * ND + c4 * 4);
            float4 vv = *(const float4*)(Vp + (size_t)(kt * 64 + rr) * ND + c4 * 4);
            *(float4*)&Ks[rr][(c4 ^ (rr >> 4)) * 4] = kv;
            *(float4*)&Vs[rr][c4 * 4] = vv;
        }
        __syncthreads();

        float p[16];
#pragma unroll
        for (int jc = 0; jc < 4; jc++) {
            float a0 = 0.f, a1 = 0.f, a2 = 0.f, a3 = 0.f;
            const int kl0 = q4 * 16 + jc * 4;
#pragma unroll
            for (int d4 = 0; d4 < 16; d4++) {
                const int pc = (d4 ^ q4) * 4;
                float4 k0v = *(const float4*)&Ks[kl0 + 0][pc];
                float4 k1v = *(const float4*)&Ks[kl0 + 1][pc];
                float4 k2v = *(const float4*)&Ks[kl0 + 2][pc];
                float4 k3v = *(const float4*)&Ks[kl0 + 3][pc];
                float q0 = qreg[d4*4+0], q1 = qreg[d4*4+1];
                float q2 = qreg[d4*4+2], q3 = qreg[d4*4+3];
                a0 += q0*k0v.x + q1*k0v.y + q2*k0v.z + q3*k0v.w;
                a1 += q0*k1v.x + q1*k1v.y + q2*k1v.z + q3*k1v.w;
                a2 += q0*k2v.x + q1*k2v.y + q2*k2v.z + q3*k2v.w;
                a3 += q0*k3v.x + q1*k3v.y + q2*k3v.z + q3*k3v.w;
            }
            p[jc*4+0] = a0 * scale; p[jc*4+1] = a1 * scale;
            p[jc*4+2] = a2 * scale; p[jc*4+3] = a3 * scale;
        }

        float tmax = p[0];
#pragma unroll
        for (int j = 1; j < 16; j++) tmax = fmaxf(tmax, p[j]);
        tmax = fmaxf(tmax, __shfl_xor_sync(0xffffffffu, tmax, 1));
        tmax = fmaxf(tmax, __shfl_xor_sync(0xffffffffu, tmax, 2));
        float m_new = fmaxf(m_i, tmax);
        float alpha = __expf(m_i - m_new);
        float lsum = 0.f;
#pragma unroll
        for (int j = 0; j < 16; j++) { p[j] = __expf(p[j] - m_new); lsum += p[j]; }
        lsum += __shfl_xor_sync(0xffffffffu, lsum, 1);
        lsum += __shfl_xor_sync(0xffffffffu, lsum, 2);
        l_i = l_i * alpha + lsum;
        m_i = m_new;
#pragma unroll
        for (int i = 0; i < 16; i++) o[i] *= alpha;

#pragma unroll
        for (int j = 0; j < 16; j++) Ps[row][q4 * 16 + j] = p[j];
        __syncthreads();

#pragma unroll
        for (int k = 0; k < 64; k++) {
            float pk = Ps[row][k];
#pragma unroll
            for (int t = 0; t < 4; t++) {
                float4 vv = *(const float4*)&Vs[k][t * 16 + q4 * 4];
                o[t*4+0] += pk * vv.x; o[t*4+1] += pk * vv.y;
                o[t*4+2] += pk * vv.z; o[t*4+3] += pk * vv.w;
            }
        }
        __syncthreads();
    }

    float inv = 1.f / l_i;
    int b = bh >> 4, h = bh & 15;
    float* dst = g_ctx + (size_t)(b * NS + s0 + row) * NE + h * ND;
#pragma unroll
    for (int t = 0; t < 4; t++) {
        float4 v;
        v.x = o[t*4+0] * inv; v.y = o[t*4+1] * inv;
        v.z = o[t*4+2] * inv; v.w = o[t*4+3] * inv;
        *(float4*)(dst + t * 16 + q4 * 4) = v;
    }
}

// ---------------------------------------------------------------------------
extern "C" void kernel_launch(void* const* d_in, const int* in_sizes, int n_in,
                              void* d_out, int out_size)
{
    const float* q  = (const float*)d_in[0];
    const float* k  = (const float*)d_in[1];
    const float* v  = (const float*)d_in[2];
    const float* Wq = (const float*)d_in[3];
    const float* bq = (const float*)d_in[4];
    const float* Wk = (const float*)d_in[5];
    const float* bk = (const float*)d_in[6];
    const float* Wv = (const float*)d_in[7];
    const float* bv = (const float*)d_in[8];
    const float* Wo = (const float*)d_in[9];
    const float* bo = (const float*)d_in[10];
    float* out = (float*)d_out;

    cudaFuncSetAttribute(gemm_mma, cudaFuncAttributeMaxDynamicSharedMemorySize, GSMEM_BYTES);

    dim3 tt(32, 8);
    transpose_kernel<<<dim3(2, 32, 16), tt>>>(Wq, 0, NE, ND);
    transpose_kernel<<<dim3(2, 32, 16), tt>>>(Wk, 1, NE, ND);
    transpose_kernel<<<dim3(2, 32, 16), tt>>>(Wv, 2, NE, ND);
    transpose_kernel<<<dim3(32, 32, 1), tt>>>(Wo, 3, NE, NE);

    dim3 ggrid(NM / 128, NE / 128);
    gemm_mma<<<ggrid, 256, GSMEM_BYTES>>>(q, bq, out, 0, 0);
    gemm_mma<<<ggrid, 256, GSMEM_BYTES>>>(k, bk, out, 1, 1);
    gemm_mma<<<ggrid, 256, GSMEM_BYTES>>>(v, bv, out, 2, 2);

    attn_kernel<<<dim3(NS / 64, NB * NH), 256>>>();

    gemm_mma<<<ggrid, 256, GSMEM_BYTES>>>(nullptr, bo, out, 3, 3);
}

// round 5
// speedup vs baseline: 4.7324x; 3.4580x over previous
#include <cuda_runtime.h>
#include <math.h>
#include <stdint.h>

#define NB 8
#define NS 1024
#define NE 1024
#define NH 16
#define ND 64
#define NM (NB*NS)

// ---------------- device-global scratch (allocation-free) ------------------
__device__ float g_qh[NB*NH*NS*ND];
__device__ float g_kh[NB*NH*NS*ND];
__device__ float g_vh[NB*NH*NS*ND];
__device__ float g_ctx[NB*NS*NE];
__device__ float g_qr[NM*NE];       // tf32-rounded inputs
__device__ float g_kr[NM*NE];
__device__ float g_vr[NM*NE];
__device__ float g_wqT[NH*ND*NE];   // [n=h*64+e][k], tf32-rounded
__device__ float g_wkT[NH*ND*NE];
__device__ float g_wvT[NH*ND*NE];
__device__ float g_woT[NE*NE];

__device__ __forceinline__ float tf32rna(float x) {
    uint32_t u;
    asm("cvt.rna.tf32.f32 %0, %1;" : "=r"(u) : "f"(x));
    return __uint_as_float(u);
}
__device__ __forceinline__ uint32_t smem_u32(const void* p) {
    uint32_t a;
    asm("{ .reg .u64 t; cvta.to.shared.u64 t, %1; cvt.u32.u64 %0, t; }" : "=r"(a) : "l"(p));
    return a;
}
__device__ __forceinline__ void cpa16(uint32_t dst, const void* src) {
    asm volatile("cp.async.cg.shared.global [%0], [%1], 16;" :: "r"(dst), "l"(src));
}
__device__ __forceinline__ void cpa_commit() {
    asm volatile("cp.async.commit_group;" ::: "memory");
}
template<int N> __device__ __forceinline__ void cpa_wait() {
    asm volatile("cp.async.wait_group %0;" :: "n"(N) : "memory");
}
__device__ __forceinline__ void mma16n8k8(float* d, const uint32_t* a, uint32_t b0, uint32_t b1) {
    asm volatile(
        "mma.sync.aligned.m16n8k8.row.col.f32.tf32.tf32.f32 "
        "{%0,%1,%2,%3}, {%4,%5,%6,%7}, {%8,%9}, {%0,%1,%2,%3};"
        : "+f"(d[0]), "+f"(d[1]), "+f"(d[2]), "+f"(d[3])
        : "r"(a[0]), "r"(a[1]), "r"(a[2]), "r"(a[3]), "r"(b0), "r"(b1));
}

// ---------------- GEMM: 128x128 tile, 4-stage cp.async, tf32 mma -----------
#define TSTRIDE 36
#define TILEF  (128*TSTRIDE)             // 4608 floats
#define STAGEF (2*TILEF)                 // 9216 floats = 36864 B
#define GSTAGES 4
#define GSMEM_BYTES (GSTAGES*STAGEF*4)   // 147456

__global__ __launch_bounds__(256, 1) void gemm_mma(
    const float* __restrict__ Ain, const float* __restrict__ bias,
    float* __restrict__ Odirect, int bsel, int osel)
{
    extern __shared__ float sm[];
    const uint32_t su = smem_u32(sm);
    const int tid  = threadIdx.x;
    const int wid  = tid >> 5;
    const int lane = tid & 31;
    const int g    = lane >> 2;
    const int t    = lane & 3;
    const int m0 = blockIdx.x * 128;
    const int n0 = blockIdx.y * 128;
    const int warp_m = (wid >> 2) * 64;
    const int warp_n = (wid & 3) * 32;

    const float* A  = Ain ? Ain : g_ctx;
    const float* BT = (bsel == 0) ? g_wqT : (bsel == 1) ? g_wkT :
                      (bsel == 2) ? g_wvT : g_woT;

    const int lrow = tid >> 3;        // 0..31
    const int lc4  = tid & 7;         // 0..7

    auto issue = [&](int c, int s) {
        const int k0 = c * 32;
        const uint32_t base = su + s * (STAGEF * 4);
#pragma unroll
        for (int i = 0; i < 4; i++) {
            int row = lrow + i * 32;
            cpa16(base + (row * TSTRIDE + lc4 * 4) * 4,
                  A + (size_t)(m0 + row) * NE + k0 + lc4 * 4);
            cpa16(base + TILEF * 4 + (row * TSTRIDE + lc4 * 4) * 4,
                  BT + (size_t)(n0 + row) * NE + k0 + lc4 * 4);
        }
    };

    issue(0, 0); cpa_commit();
    issue(1, 1); cpa_commit();
    issue(2, 2); cpa_commit();

    float d[4][4][4];
#pragma unroll
    for (int mi = 0; mi < 4; mi++)
#pragma unroll
        for (int ni = 0; ni < 4; ni++)
#pragma unroll
            for (int j = 0; j < 4; j++) d[mi][ni][j] = 0.f;

    for (int c = 0; c < 32; c++) {
        if (c < 30) cpa_wait<2>(); else if (c == 30) cpa_wait<1>(); else cpa_wait<0>();
        __syncthreads();
        if (c + 3 < 32) { issue(c + 3, (c + 3) & 3); cpa_commit(); }

        const int st = c & 3;
        const float* As = sm + st * STAGEF + (warp_m + g) * TSTRIDE;
        const float* Bs = sm + st * STAGEF + TILEF + (warp_n + g) * TSTRIDE;
#pragma unroll
        for (int ks = 0; ks < 4; ks++) {
            const int k0 = ks * 8 + t;
            uint32_t a[4][4];
#pragma unroll
            for (int mi = 0; mi < 4; mi++) {
                const float* ap = As + mi * 16 * TSTRIDE + k0;
                a[mi][0] = __float_as_uint(ap[0]);
                a[mi][1] = __float_as_uint(ap[8 * TSTRIDE]);
                a[mi][2] = __float_as_uint(ap[4]);
                a[mi][3] = __float_as_uint(ap[8 * TSTRIDE + 4]);
            }
#pragma unroll
            for (int ni = 0; ni < 4; ni++) {
                const float* bp = Bs + ni * 8 * TSTRIDE + k0;
                uint32_t b0 = __float_as_uint(bp[0]);
                uint32_t b1 = __float_as_uint(bp[4]);
#pragma unroll
                for (int mi = 0; mi < 4; mi++)
                    mma16n8k8(d[mi][ni], a[mi], b0, b1);
            }
        }
    }

    // epilogue: bias + store (proj outputs rounded to tf32 for downstream mma)
    float* ob = (osel == 0) ? g_qh : (osel == 1) ? g_kh :
                (osel == 2) ? g_vh : Odirect;
#pragma unroll
    for (int mi = 0; mi < 4; mi++) {
#pragma unroll
        for (int ni = 0; ni < 4; ni++) {
            const int r0  = m0 + warp_m + mi * 16 + g;
            const int r1  = r0 + 8;
            const int col = n0 + warp_n + ni * 8 + t * 2;
            const float bx = bias[col], by = bias[col + 1];
            float2 v0, v1;
            v0.x = d[mi][ni][0] + bx; v0.y = d[mi][ni][1] + by;
            v1.x = d[mi][ni][2] + bx; v1.y = d[mi][ni][3] + by;
            if (osel < 3) {
                v0.x = tf32rna(v0.x); v0.y = tf32rna(v0.y);
                v1.x = tf32rna(v1.x); v1.y = tf32rna(v1.y);
                const int h = col >> 6, e = col & 63;
                float* d0 = ob + ((size_t)((r0 >> 10) * NH + h) * NS + (r0 & 1023)) * ND + e;
                float* d1 = ob + ((size_t)((r1 >> 10) * NH + h) * NS + (r1 & 1023)) * ND + e;
                *(float2*)d0 = v0;
                *(float2*)d1 = v1;
            } else {
                *(float2*)(ob + (size_t)r0 * NE + col) = v0;
                *(float2*)(ob + (size_t)r1 * NE + col) = v1;
            }
        }
    }
}

// ---------------- attention: tf32 mma flash, 128-row Q tile ----------------
#define KSTR 68
#define VSTR 72
#define QPF  (128*KSTR)                 // 8704 floats (Q, reused as P)
#define KVF  (64*KSTR + 64*VSTR)        // 8960 floats per stage
#define ASMEM_BYTES ((QPF + 3*KVF)*4)   // 142336

__global__ __launch_bounds__(256, 1) void attn_mma()
{
    extern __shared__ float smf[];
    const uint32_t su = smem_u32(smf);
    const int tid = threadIdx.x, wid = tid >> 5, lane = tid & 31;
    const int g = lane >> 2, t = lane & 3;
    const int bh = blockIdx.y;
    const int s0 = blockIdx.x * 128;
    const int w16 = wid * 16;
    const float* Qp = g_qh + (size_t)bh * NS * ND;
    const float* Kp = g_kh + (size_t)bh * NS * ND;
    const float* Vp = g_vh + (size_t)bh * NS * ND;

    const int lkv = tid >> 4;          // 0..15
    const int lc4 = tid & 15;          // 0..15

    auto issue_kv = [&](int kt, int st) {
        const uint32_t kB = su + QPF * 4 + st * (KVF * 4);
        const uint32_t vB = kB + 64 * KSTR * 4;
        const float* Ks = Kp + (size_t)kt * 64 * ND;
        const float* Vs = Vp + (size_t)kt * 64 * ND;
#pragma unroll
        for (int i = 0; i < 4; i++) {
            int kv = lkv + i * 16;
            cpa16(kB + (kv * KSTR + lc4 * 4) * 4, Ks + (size_t)kv * ND + lc4 * 4);
            cpa16(vB + (kv * VSTR + lc4 * 4) * 4, Vs + (size_t)kv * ND + lc4 * 4);
        }
    };

    issue_kv(0, 0); cpa_commit();
    issue_kv(1, 1); cpa_commit();

    // Q tile -> smem (stride 68)
#pragma unroll
    for (int i = 0; i < 8; i++) {
        int idx = tid + i * 256;
        int row = idx >> 4, c4 = idx & 15;
        *(float4*)(smf + row * KSTR + c4 * 4) =
            *(const float4*)(Qp + (size_t)(s0 + row) * ND + c4 * 4);
    }
    __syncthreads();

    // persistent Q fragments
    uint32_t qf[8][4];
    {
        const float* qp = smf + (w16 + g) * KSTR;
#pragma unroll
        for (int ks = 0; ks < 8; ks++) {
            qf[ks][0] = __float_as_uint(qp[ks * 8 + t]);
            qf[ks][1] = __float_as_uint(qp[8 * KSTR + ks * 8 + t]);
            qf[ks][2] = __float_as_uint(qp[ks * 8 + t + 4]);
            qf[ks][3] = __float_as_uint(qp[8 * KSTR + ks * 8 + t + 4]);
        }
    }

    float o[8][4];
#pragma unroll
    for (int ni = 0; ni < 8; ni++)
#pragma unroll
        for (int j = 0; j < 4; j++) o[ni][j] = 0.f;
    float mA = -1e30f, mB = -1e30f, lA = 0.f, lB = 0.f;
    const float scale = 0.125f;

    for (int kt = 0; kt < 16; kt++) {
        if (kt < 15) cpa_wait<1>(); else cpa_wait<0>();
        __syncthreads();
        if (kt + 2 < 16) { issue_kv(kt + 2, (kt + 2) % 3); cpa_commit(); }

        const int st = kt % 3;
        const float* sK = smf + QPF + st * KVF;
        const float* sV = sK + 64 * KSTR;

        // S = Q @ K^T
        float s[8][4];
#pragma unroll
        for (int ni = 0; ni < 8; ni++)
#pragma unroll
            for (int j = 0; j < 4; j++) s[ni][j] = 0.f;
#pragma unroll
        for (int ks = 0; ks < 8; ks++) {
            const float* kp = sK + ks * 8 + t;
#pragma unroll
            for (int ni = 0; ni < 8; ni++) {
                uint32_t b0 = __float_as_uint(kp[(ni * 8 + g) * KSTR]);
                uint32_t b1 = __float_as_uint(kp[(ni * 8 + g) * KSTR + 4]);
                mma16n8k8(s[ni], qf[ks], b0, b1);
            }
        }

        // online softmax (rows g and g+8)
        float mxA = -1e30f, mxB = -1e30f;
#pragma unroll
        for (int ni = 0; ni < 8; ni++) {
            mxA = fmaxf(mxA, fmaxf(s[ni][0], s[ni][1]));
            mxB = fmaxf(mxB, fmaxf(s[ni][2], s[ni][3]));
        }
        mxA = fmaxf(mxA, __shfl_xor_sync(0xffffffffu, mxA, 1));
        mxA = fmaxf(mxA, __shfl_xor_sync(0xffffffffu, mxA, 2));
        mxB = fmaxf(mxB, __shfl_xor_sync(0xffffffffu, mxB, 1));
        mxB = fmaxf(mxB, __shfl_xor_sync(0xffffffffu, mxB, 2));
        float mAn = fmaxf(mA, mxA * scale);
        float mBn = fmaxf(mB, mxB * scale);
        float aA = __expf(mA - mAn), aB = __expf(mB - mBn);
        float sumA = 0.f, sumB = 0.f;
#pragma unroll
        for (int ni = 0; ni < 8; ni++) {
            s[ni][0] = __expf(s[ni][0] * scale - mAn);
            s[ni][1] = __expf(s[ni][1] * scale - mAn);
            s[ni][2] = __expf(s[ni][2] * scale - mBn);
            s[ni][3] = __expf(s[ni][3] * scale - mBn);
            sumA += s[ni][0] + s[ni][1];
            sumB += s[ni][2] + s[ni][3];
        }
        sumA += __shfl_xor_sync(0xffffffffu, sumA, 1);
        sumA += __shfl_xor_sync(0xffffffffu, sumA, 2);
        sumB += __shfl_xor_sync(0xffffffffu, sumB, 1);
        sumB += __shfl_xor_sync(0xffffffffu, sumB, 2);
        lA = lA * aA + sumA; lB = lB * aB + sumB;
        mA = mAn; mB = mBn;
#pragma unroll
        for (int ni = 0; ni < 8; ni++) {
            o[ni][0] *= aA; o[ni][1] *= aA;
            o[ni][2] *= aB; o[ni][3] *= aB;
        }

        // publish P (tf32-rounded) into QP buffer (own warp's rows)
        float* pr = smf + (w16 + g) * KSTR;
        __syncwarp();
#pragma unroll
        for (int ni = 0; ni < 8; ni++) {
            float2 v0; v0.x = tf32rna(s[ni][0]); v0.y = tf32rna(s[ni][1]);
            float2 v1; v1.x = tf32rna(s[ni][2]); v1.y = tf32rna(s[ni][3]);
            *(float2*)(pr + ni * 8 + 2 * t) = v0;
            *(float2*)(pr + 8 * KSTR + ni * 8 + 2 * t) = v1;
        }
        __syncwarp();

        // O += P @ V
#pragma unroll
        for (int ks = 0; ks < 8; ks++) {
            uint32_t a[4];
            a[0] = __float_as_uint(pr[ks * 8 + t]);
            a[1] = __float_as_uint(pr[8 * KSTR + ks * 8 + t]);
            a[2] = __float_as_uint(pr[ks * 8 + t + 4]);
            a[3] = __float_as_uint(pr[8 * KSTR + ks * 8 + t + 4]);
            const float* vp = sV + (ks * 8 + t) * VSTR;
#pragma unroll
            for (int ni = 0; ni < 8; ni++) {
                uint32_t b0 = __float_as_uint(vp[ni * 8 + g]);
                uint32_t b1 = __float_as_uint(vp[4 * VSTR + ni * 8 + g]);
                mma16n8k8(o[ni], a, b0, b1);
            }
        }
    }

    // epilogue: normalize, round, write ctx
    const float iA = 1.f / lA, iB = 1.f / lB;
    const int b = bh >> 4, h = bh & 15;
    const int rA = s0 + w16 + g, rB = rA + 8;
    float* dA = g_ctx + (size_t)(b * NS + rA) * NE + h * 64;
    float* dB = g_ctx + (size_t)(b * NS + rB) * NE + h * 64;
#pragma unroll
    for (int ni = 0; ni < 8; ni++) {
        float2 vA, vB2;
        vA.x  = tf32rna(o[ni][0] * iA); vA.y  = tf32rna(o[ni][1] * iA);
        vB2.x = tf32rna(o[ni][2] * iB); vB2.y = tf32rna(o[ni][3] * iB);
        *(float2*)(dA + ni * 8 + 2 * t) = vA;
        *(float2*)(dB + ni * 8 + 2 * t) = vB2;
    }
}

// ---------------- small prep kernels ----------------------------------------
__global__ void round_kernel(const float* __restrict__ in, float* __restrict__ out, int n4)
{
    int i = blockIdx.x * blockDim.x + threadIdx.x;
    for (; i < n4; i += gridDim.x * blockDim.x) {
        float4 v = ((const float4*)in)[i];
        v.x = tf32rna(v.x); v.y = tf32rna(v.y);
        v.z = tf32rna(v.z); v.w = tf32rna(v.w);
        ((float4*)out)[i] = v;
    }
}

__global__ void transpose_kernel(const float* __restrict__ in, int sel, int R, int C)
{
    __shared__ float tbuf[32][33];
    float* out = (sel == 0) ? g_wqT : (sel == 1) ? g_wkT : (sel == 2) ? g_wvT : g_woT;
    const float* I = in  + (size_t)blockIdx.z * R * C;
    float*       O = out + (size_t)blockIdx.z * R * C;
    int c0 = blockIdx.x * 32, r0 = blockIdx.y * 32;
#pragma unroll
    for (int j = threadIdx.y; j < 32; j += 8)
        tbuf[j][threadIdx.x] = I[(size_t)(r0 + j) * C + c0 + threadIdx.x];
    __syncthreads();
#pragma unroll
    for (int j = threadIdx.y; j < 32; j += 8)
        O[(size_t)(c0 + j) * R + r0 + threadIdx.x] = tf32rna(tbuf[threadIdx.x][j]);
}

// ---------------------------------------------------------------------------
extern "C" void kernel_launch(void* const* d_in, const int* in_sizes, int n_in,
                              void* d_out, int out_size)
{
    const float* q  = (const float*)d_in[0];
    const float* k  = (const float*)d_in[1];
    const float* v  = (const float*)d_in[2];
    const float* Wq = (const float*)d_in[3];
    const float* bq = (const float*)d_in[4];
    const float* Wk = (const float*)d_in[5];
    const float* bk = (const float*)d_in[6];
    const float* Wv = (const float*)d_in[7];
    const float* bv = (const float*)d_in[8];
    const float* Wo = (const float*)d_in[9];
    const float* bo = (const float*)d_in[10];
    float* out = (float*)d_out;

    cudaFuncSetAttribute(gemm_mma, cudaFuncAttributeMaxDynamicSharedMemorySize, GSMEM_BYTES);
    cudaFuncSetAttribute(attn_mma, cudaFuncAttributeMaxDynamicSharedMemorySize, ASMEM_BYTES);

    float *gqr, *gkr, *gvr;
    cudaGetSymbolAddress((void**)&gqr, g_qr);
    cudaGetSymbolAddress((void**)&gkr, g_kr);
    cudaGetSymbolAddress((void**)&gvr, g_vr);

    const int n4 = NM * NE / 4;
    round_kernel<<<2048, 256>>>(q, gqr, n4);
    round_kernel<<<2048, 256>>>(k, gkr, n4);
    round_kernel<<<2048, 256>>>(v, gvr, n4);

    dim3 tt(32, 8);
    transpose_kernel<<<dim3(2, 32, 16), tt>>>(Wq, 0, NE, ND);
    transpose_kernel<<<dim3(2, 32, 16), tt>>>(Wk, 1, NE, ND);
    transpose_kernel<<<dim3(2, 32, 16), tt>>>(Wv, 2, NE, ND);
    transpose_kernel<<<dim3(32, 32, 1), tt>>>(Wo, 3, NE, NE);

    dim3 ggrid(NM / 128, NE / 128);
    gemm_mma<<<ggrid, 256, GSMEM_BYTES>>>(gqr, bq, out, 0, 0);
    gemm_mma<<<ggrid, 256, GSMEM_BYTES>>>(gkr, bk, out, 1, 1);
    gemm_mma<<<ggrid, 256, GSMEM_BYTES>>>(gvr, bv, out, 2, 2);

    attn_mma<<<dim3(NS / 128, NB * NH), 256, ASMEM_BYTES>>>();

    gemm_mma<<<ggrid, 256, GSMEM_BYTES>>>(nullptr, bo, out, 3, 3);
}

// round 6
// speedup vs baseline: 5.6980x; 1.2040x over previous
#include <cuda_runtime.h>
#include <math.h>
#include <stdint.h>

#define NB 8
#define NS 1024
#define NE 1024
#define NH 16
#define ND 64
#define NM (NB*NS)

// ---------------- device-global scratch (allocation-free) ------------------
__device__ float g_qh[NB*NH*NS*ND];
__device__ float g_kh[NB*NH*NS*ND];
__device__ float g_vh[NB*NH*NS*ND];
__device__ float g_ctx[NB*NS*NE];
__device__ float g_qr[NM*NE];       // tf32-rounded inputs
__device__ float g_kr[NM*NE];
__device__ float g_vr[NM*NE];
__device__ float g_wqT[NH*ND*NE];   // [n=h*64+e][k], tf32-rounded
__device__ float g_wkT[NH*ND*NE];
__device__ float g_wvT[NH*ND*NE];
__device__ float g_woT[NE*NE];

__device__ __forceinline__ float tf32rna(float x) {
    uint32_t u;
    asm("cvt.rna.tf32.f32 %0, %1;" : "=r"(u) : "f"(x));
    return __uint_as_float(u);
}
__device__ __forceinline__ uint32_t smem_u32(const void* p) {
    uint32_t a;
    asm("{ .reg .u64 t; cvta.to.shared.u64 t, %1; cvt.u32.u64 %0, t; }" : "=r"(a) : "l"(p));
    return a;
}
__device__ __forceinline__ void cpa16(uint32_t dst, const void* src) {
    asm volatile("cp.async.cg.shared.global [%0], [%1], 16;" :: "r"(dst), "l"(src));
}
__device__ __forceinline__ void cpa_commit() {
    asm volatile("cp.async.commit_group;" ::: "memory");
}
template<int N> __device__ __forceinline__ void cpa_wait() {
    asm volatile("cp.async.wait_group %0;" :: "n"(N) : "memory");
}
__device__ __forceinline__ void mma16n8k8(float* d, const uint32_t* a, uint32_t b0, uint32_t b1) {
    asm volatile(
        "mma.sync.aligned.m16n8k8.row.col.f32.tf32.tf32.f32 "
        "{%0,%1,%2,%3}, {%4,%5,%6,%7}, {%8,%9}, {%0,%1,%2,%3};"
        : "+f"(d[0]), "+f"(d[1]), "+f"(d[2]), "+f"(d[3])
        : "r"(a[0]), "r"(a[1]), "r"(a[2]), "r"(a[3]), "r"(b0), "r"(b1));
}

// ---------------- GEMM: 128x128 tile, 3-stage cp.async, tf32 mma -----------
#define TSTRIDE 36
#define TILEF  (128*TSTRIDE)             // 4608 floats
#define STAGEF (2*TILEF)                 // 9216 floats = 36864 B
#define GSTAGES 3
#define GSMEM_BYTES (GSTAGES*STAGEF*4)   // 110592 -> 2 CTAs/SM

__device__ __forceinline__ void gemm_body(
    const float* __restrict__ A, const float* __restrict__ BT,
    const float* __restrict__ bias, float* __restrict__ ob, int osel,
    float* sm)
{
    const uint32_t su = smem_u32(sm);
    const int tid  = threadIdx.x;
    const int wid  = tid >> 5;
    const int lane = tid & 31;
    const int g    = lane >> 2;
    const int t    = lane & 3;
    const int m0 = blockIdx.x * 128;
    const int n0 = blockIdx.y * 128;
    const int warp_m = (wid >> 2) * 64;
    const int warp_n = (wid & 3) * 32;

    const int lrow = tid >> 3;        // 0..31
    const int lc4  = tid & 7;         // 0..7

    auto issue = [&](int c, int s) {
        const int k0 = c * 32;
        const uint32_t base = su + s * (STAGEF * 4);
#pragma unroll
        for (int i = 0; i < 4; i++) {
            int row = lrow + i * 32;
            cpa16(base + (row * TSTRIDE + lc4 * 4) * 4,
                  A + (size_t)(m0 + row) * NE + k0 + lc4 * 4);
            cpa16(base + TILEF * 4 + (row * TSTRIDE + lc4 * 4) * 4,
                  BT + (size_t)(n0 + row) * NE + k0 + lc4 * 4);
        }
    };

    issue(0, 0); cpa_commit();
    issue(1, 1); cpa_commit();

    float d[4][4][4];
#pragma unroll
    for (int mi = 0; mi < 4; mi++)
#pragma unroll
        for (int ni = 0; ni < 4; ni++)
#pragma unroll
            for (int j = 0; j < 4; j++) d[mi][ni][j] = 0.f;

    for (int c = 0; c < 32; c++) {
        if (c + 2 < 32) { issue(c + 2, (c + 2) % 3); cpa_commit(); }
        if (c < 30) cpa_wait<2>(); else if (c == 30) cpa_wait<1>(); else cpa_wait<0>();
        __syncthreads();

        const int st = c % 3;
        const float* As = sm + st * STAGEF + (warp_m + g) * TSTRIDE;
        const float* Bs = sm + st * STAGEF + TILEF + (warp_n + g) * TSTRIDE;
#pragma unroll
        for (int ks = 0; ks < 4; ks++) {
            const int k0 = ks * 8 + t;
            uint32_t a[4][4];
#pragma unroll
            for (int mi = 0; mi < 4; mi++) {
                const float* ap = As + mi * 16 * TSTRIDE + k0;
                a[mi][0] = __float_as_uint(ap[0]);
                a[mi][1] = __float_as_uint(ap[8 * TSTRIDE]);
                a[mi][2] = __float_as_uint(ap[4]);
                a[mi][3] = __float_as_uint(ap[8 * TSTRIDE + 4]);
            }
#pragma unroll
            for (int ni = 0; ni < 4; ni++) {
                const float* bp = Bs + ni * 8 * TSTRIDE + k0;
                uint32_t b0 = __float_as_uint(bp[0]);
                uint32_t b1 = __float_as_uint(bp[4]);
#pragma unroll
                for (int mi = 0; mi < 4; mi++)
                    mma16n8k8(d[mi][ni], a[mi], b0, b1);
            }
        }
        __syncthreads();
    }

    // epilogue: bias + store (proj outputs rounded to tf32 for downstream mma)
#pragma unroll
    for (int mi = 0; mi < 4; mi++) {
#pragma unroll
        for (int ni = 0; ni < 4; ni++) {
            const int r0  = m0 + warp_m + mi * 16 + g;
            const int r1  = r0 + 8;
            const int col = n0 + warp_n + ni * 8 + t * 2;
            const float bx = bias[col], by = bias[col + 1];
            float2 v0, v1;
            v0.x = d[mi][ni][0] + bx; v0.y = d[mi][ni][1] + by;
            v1.x = d[mi][ni][2] + bx; v1.y = d[mi][ni][3] + by;
            if (osel < 3) {
                v0.x = tf32rna(v0.x); v0.y = tf32rna(v0.y);
                v1.x = tf32rna(v1.x); v1.y = tf32rna(v1.y);
                const int h = col >> 6, e = col & 63;
                float* d0 = ob + ((size_t)((r0 >> 10) * NH + h) * NS + (r0 & 1023)) * ND + e;
                float* d1 = ob + ((size_t)((r1 >> 10) * NH + h) * NS + (r1 & 1023)) * ND + e;
                *(float2*)d0 = v0;
                *(float2*)d1 = v1;
            } else {
                *(float2*)(ob + (size_t)r0 * NE + col) = v0;
                *(float2*)(ob + (size_t)r1 * NE + col) = v1;
            }
        }
    }
}

// fused Q/K/V projection GEMMs: blockIdx.z = 0/1/2
__global__ __launch_bounds__(256, 2) void proj_gemm(
    const float* __restrict__ bq, const float* __restrict__ bk,
    const float* __restrict__ bv)
{
    extern __shared__ float sm[];
    const int z = blockIdx.z;
    const float* A  = (z == 0) ? g_qr  : (z == 1) ? g_kr  : g_vr;
    const float* BT = (z == 0) ? g_wqT : (z == 1) ? g_wkT : g_wvT;
    const float* bias = (z == 0) ? bq : (z == 1) ? bk : bv;
    float* ob = (z == 0) ? g_qh : (z == 1) ? g_kh : g_vh;
    gemm_body(A, BT, bias, ob, z, sm);
}

__global__ __launch_bounds__(256, 2) void out_gemm(
    const float* __restrict__ bo, float* __restrict__ out)
{
    extern __shared__ float sm[];
    gemm_body(g_ctx, g_woT, bo, out, 3, sm);
}

// ---------------- attention: tf32 mma flash, 128-row Q tile ----------------
#define KSTR 68
#define VSTR 72
#define QPF  (128*KSTR)                 // 8704 floats (Q, reused as P)
#define KVF  (64*KSTR + 64*VSTR)        // 8960 floats per stage
#define ASTAGES 2
#define ASMEM_BYTES ((QPF + ASTAGES*KVF)*4)  // 106496 -> 2 CTAs/SM

__global__ __launch_bounds__(256, 2) void attn_mma()
{
    extern __shared__ float smf[];
    const uint32_t su = smem_u32(smf);
    const int tid = threadIdx.x, wid = tid >> 5, lane = tid & 31;
    const int g = lane >> 2, t = lane & 3;
    const int bh = blockIdx.y;
    const int s0 = blockIdx.x * 128;
    const int w16 = wid * 16;
    const float* Qp = g_qh + (size_t)bh * NS * ND;
    const float* Kp = g_kh + (size_t)bh * NS * ND;
    const float* Vp = g_vh + (size_t)bh * NS * ND;

    const int lkv = tid >> 4;          // 0..15
    const int lc4 = tid & 15;          // 0..15

    auto issue_kv = [&](int kt, int st) {
        const uint32_t kB = su + QPF * 4 + st * (KVF * 4);
        const uint32_t vB = kB + 64 * KSTR * 4;
        const float* Ks = Kp + (size_t)kt * 64 * ND;
        const float* Vs = Vp + (size_t)kt * 64 * ND;
#pragma unroll
        for (int i = 0; i < 4; i++) {
            int kv = lkv + i * 16;
            cpa16(kB + (kv * KSTR + lc4 * 4) * 4, Ks + (size_t)kv * ND + lc4 * 4);
            cpa16(vB + (kv * VSTR + lc4 * 4) * 4, Vs + (size_t)kv * ND + lc4 * 4);
        }
    };

    issue_kv(0, 0); cpa_commit();

    // Q tile -> smem (stride 68)
#pragma unroll
    for (int i = 0; i < 8; i++) {
        int idx = tid + i * 256;
        int row = idx >> 4, c4 = idx & 15;
        *(float4*)(smf + row * KSTR + c4 * 4) =
            *(const float4*)(Qp + (size_t)(s0 + row) * ND + c4 * 4);
    }
    __syncthreads();

    // persistent Q fragments
    uint32_t qf[8][4];
    {
        const float* qp = smf + (w16 + g) * KSTR;
#pragma unroll
        for (int ks = 0; ks < 8; ks++) {
            qf[ks][0] = __float_as_uint(qp[ks * 8 + t]);
            qf[ks][1] = __float_as_uint(qp[8 * KSTR + ks * 8 + t]);
            qf[ks][2] = __float_as_uint(qp[ks * 8 + t + 4]);
            qf[ks][3] = __float_as_uint(qp[8 * KSTR + ks * 8 + t + 4]);
        }
    }

    float o[8][4];
#pragma unroll
    for (int ni = 0; ni < 8; ni++)
#pragma unroll
        for (int j = 0; j < 4; j++) o[ni][j] = 0.f;
    float mA = -1e30f, mB = -1e30f, lA = 0.f, lB = 0.f;
    const float scale = 0.125f;

    for (int kt = 0; kt < 16; kt++) {
        if (kt + 1 < 16) { issue_kv(kt + 1, (kt + 1) & 1); cpa_commit(); }
        if (kt < 15) cpa_wait<1>(); else cpa_wait<0>();
        __syncthreads();

        const int st = kt & 1;
        const float* sK = smf + QPF + st * KVF;
        const float* sV = sK + 64 * KSTR;

        // S = Q @ K^T
        float s[8][4];
#pragma unroll
        for (int ni = 0; ni < 8; ni++)
#pragma unroll
            for (int j = 0; j < 4; j++) s[ni][j] = 0.f;
#pragma unroll
        for (int ks = 0; ks < 8; ks++) {
            const float* kp = sK + ks * 8 + t;
#pragma unroll
            for (int ni = 0; ni < 8; ni++) {
                uint32_t b0 = __float_as_uint(kp[(ni * 8 + g) * KSTR]);
                uint32_t b1 = __float_as_uint(kp[(ni * 8 + g) * KSTR + 4]);
                mma16n8k8(s[ni], qf[ks], b0, b1);
            }
        }

        // online softmax (rows g and g+8)
        float mxA = -1e30f, mxB = -1e30f;
#pragma unroll
        for (int ni = 0; ni < 8; ni++) {
            mxA = fmaxf(mxA, fmaxf(s[ni][0], s[ni][1]));
            mxB = fmaxf(mxB, fmaxf(s[ni][2], s[ni][3]));
        }
        mxA = fmaxf(mxA, __shfl_xor_sync(0xffffffffu, mxA, 1));
        mxA = fmaxf(mxA, __shfl_xor_sync(0xffffffffu, mxA, 2));
        mxB = fmaxf(mxB, __shfl_xor_sync(0xffffffffu, mxB, 1));
        mxB = fmaxf(mxB, __shfl_xor_sync(0xffffffffu, mxB, 2));
        float mAn = fmaxf(mA, mxA * scale);
        float mBn = fmaxf(mB, mxB * scale);
        float aA = __expf(mA - mAn), aB = __expf(mB - mBn);
        float sumA = 0.f, sumB = 0.f;
#pragma unroll
        for (int ni = 0; ni < 8; ni++) {
            s[ni][0] = __expf(s[ni][0] * scale - mAn);
            s[ni][1] = __expf(s[ni][1] * scale - mAn);
            s[ni][2] = __expf(s[ni][2] * scale - mBn);
            s[ni][3] = __expf(s[ni][3] * scale - mBn);
            sumA += s[ni][0] + s[ni][1];
            sumB += s[ni][2] + s[ni][3];
        }
        sumA += __shfl_xor_sync(0xffffffffu, sumA, 1);
        sumA += __shfl_xor_sync(0xffffffffu, sumA, 2);
        sumB += __shfl_xor_sync(0xffffffffu, sumB, 1);
        sumB += __shfl_xor_sync(0xffffffffu, sumB, 2);
        lA = lA * aA + sumA; lB = lB * aB + sumB;
        mA = mAn; mB = mBn;
#pragma unroll
        for (int ni = 0; ni < 8; ni++) {
            o[ni][0] *= aA; o[ni][1] *= aA;
            o[ni][2] *= aB; o[ni][3] *= aB;
        }

        // publish P (tf32-rounded) into QP buffer (own warp's rows)
        float* pr = smf + (w16 + g) * KSTR;
        __syncwarp();
#pragma unroll
        for (int ni = 0; ni < 8; ni++) {
            float2 v0; v0.x = tf32rna(s[ni][0]); v0.y = tf32rna(s[ni][1]);
            float2 v1; v1.x = tf32rna(s[ni][2]); v1.y = tf32rna(s[ni][3]);
            *(float2*)(pr + ni * 8 + 2 * t) = v0;
            *(float2*)(pr + 8 * KSTR + ni * 8 + 2 * t) = v1;
        }
        __syncwarp();

        // O += P @ V
#pragma unroll
        for (int ks = 0; ks < 8; ks++) {
            uint32_t a[4];
            a[0] = __float_as_uint(pr[ks * 8 + t]);
            a[1] = __float_as_uint(pr[8 * KSTR + ks * 8 + t]);
            a[2] = __float_as_uint(pr[ks * 8 + t + 4]);
            a[3] = __float_as_uint(pr[8 * KSTR + ks * 8 + t + 4]);
            const float* vp = sV + (ks * 8 + t) * VSTR;
#pragma unroll
            for (int ni = 0; ni < 8; ni++) {
                uint32_t b0 = __float_as_uint(vp[ni * 8 + g]);
                uint32_t b1 = __float_as_uint(vp[4 * VSTR + ni * 8 + g]);
                mma16n8k8(o[ni], a, b0, b1);
            }
        }
        __syncthreads();
    }

    // epilogue: normalize, round, write ctx
    const float iA = 1.f / lA, iB = 1.f / lB;
    const int b = bh >> 4, h = bh & 15;
    const int rA = s0 + w16 + g, rB = rA + 8;
    float* dA = g_ctx + (size_t)(b * NS + rA) * NE + h * 64;
    float* dB = g_ctx + (size_t)(b * NS + rB) * NE + h * 64;
#pragma unroll
    for (int ni = 0; ni < 8; ni++) {
        float2 vA, vB2;
        vA.x  = tf32rna(o[ni][0] * iA); vA.y  = tf32rna(o[ni][1] * iA);
        vB2.x = tf32rna(o[ni][2] * iB); vB2.y = tf32rna(o[ni][3] * iB);
        *(float2*)(dA + ni * 8 + 2 * t) = vA;
        *(float2*)(dB + ni * 8 + 2 * t) = vB2;
    }
}

// ---------------- small prep kernels ----------------------------------------
__global__ void round_kernel(const float* __restrict__ q, const float* __restrict__ k,
                             const float* __restrict__ v, int n4)
{
    const int z = blockIdx.z;
    const float* in = (z == 0) ? q : (z == 1) ? k : v;
    float* out = (z == 0) ? g_qr : (z == 1) ? g_kr : g_vr;
    int i = blockIdx.x * blockDim.x + threadIdx.x;
    for (; i < n4; i += gridDim.x * blockDim.x) {
        float4 w = ((const float4*)in)[i];
        w.x = tf32rna(w.x); w.y = tf32rna(w.y);
        w.z = tf32rna(w.z); w.w = tf32rna(w.w);
        ((float4*)out)[i] = w;
    }
}

__global__ void transpose_kernel(const float* __restrict__ in, int sel, int R, int C)
{
    __shared__ float tbuf[32][33];
    float* out = (sel == 0) ? g_wqT : (sel == 1) ? g_wkT : (sel == 2) ? g_wvT : g_woT;
    const float* I = in  + (size_t)blockIdx.z * R * C;
    float*       O = out + (size_t)blockIdx.z * R * C;
    int c0 = blockIdx.x * 32, r0 = blockIdx.y * 32;
#pragma unroll
    for (int j = threadIdx.y; j < 32; j += 8)
        tbuf[j][threadIdx.x] = I[(size_t)(r0 + j) * C + c0 + threadIdx.x];
    __syncthreads();
#pragma unroll
    for (int j = threadIdx.y; j < 32; j += 8)
        O[(size_t)(c0 + j) * R + r0 + threadIdx.x] = tf32rna(tbuf[threadIdx.x][j]);
}

// ---------------------------------------------------------------------------
extern "C" void kernel_launch(void* const* d_in, const int* in_sizes, int n_in,
                              void* d_out, int out_size)
{
    const float* q  = (const float*)d_in[0];
    const float* k  = (const float*)d_in[1];
    const float* v  = (const float*)d_in[2];
    const float* Wq = (const float*)d_in[3];
    const float* bq = (const float*)d_in[4];
    const float* Wk = (const float*)d_in[5];
    const float* bk = (const float*)d_in[6];
    const float* Wv = (const float*)d_in[7];
    const float* bv = (const float*)d_in[8];
    const float* Wo = (const float*)d_in[9];
    const float* bo = (const float*)d_in[10];
    float* out = (float*)d_out;

    cudaFuncSetAttribute(proj_gemm, cudaFuncAttributeMaxDynamicSharedMemorySize, GSMEM_BYTES);
    cudaFuncSetAttribute(out_gemm,  cudaFuncAttributeMaxDynamicSharedMemorySize, GSMEM_BYTES);
    cudaFuncSetAttribute(attn_mma,  cudaFuncAttributeMaxDynamicSharedMemorySize, ASMEM_BYTES);

    const int n4 = NM * NE / 4;
    round_kernel<<<dim3(512, 1, 3), 256>>>(q, k, v, n4);

    dim3 tt(32, 8);
    transpose_kernel<<<dim3(2, 32, 16), tt>>>(Wq, 0, NE, ND);
    transpose_kernel<<<dim3(2, 32, 16), tt>>>(Wk, 1, NE, ND);
    transpose_kernel<<<dim3(2, 32, 16), tt>>>(Wv, 2, NE, ND);
    transpose_kernel<<<dim3(32, 32, 1), tt>>>(Wo, 3, NE, NE);

    proj_gemm<<<dim3(NM / 128, NE / 128, 3), 256, GSMEM_BYTES>>>(bq, bk, bv);

    attn_mma<<<dim3(NS / 128, NB * NH), 256, ASMEM_BYTES>>>();

    out_gemm<<<dim3(NM / 128, NE / 128), 256, GSMEM_BYTES>>>(bo, out);
}